// round 4
// baseline (speedup 1.0000x reference)
#include <cuda_runtime.h>
#include <climits>

#define NB 32
#define H 512
#define W 512
#define OUTD 400
#define THRESH 0.7f
#define PARTS 16           // bounds blocks per batch
#define BLK_PER_BATCH 1875 // 400*400*3 / 256

// Per-(batch,part) partial bounds: {rmin, rmax, cmin, cmax}. rmax = -1 => no hit.
__device__ int4 g_part[NB * PARTS];

// Accumulate one float4 mask quad into the running bounds.
__device__ __forceinline__ void acc_quad(const float4 v, const int q,
                                         int& rmin, int& rmax,
                                         int& cmin, int& cmax) {
    if (v.x > THRESH || v.y > THRESH || v.z > THRESH || v.w > THRESH) {
        const int e = q * 4;
        const int h = e >> 9;     // W = 512
        const int w = e & 511;    // quads never straddle a row (512 % 4 == 0)
        rmin = min(rmin, h); rmax = max(rmax, h);
        if (v.x > THRESH) { cmin = min(cmin, w    ); cmax = max(cmax, w    ); }
        if (v.y > THRESH) { cmin = min(cmin, w + 1); cmax = max(cmax, w + 1); }
        if (v.z > THRESH) { cmin = min(cmin, w + 2); cmax = max(cmax, w + 2); }
        if (v.w > THRESH) { cmin = min(cmin, w + 3); cmax = max(cmax, w + 3); }
    }
}

// ---------------------------------------------------------------------------
// Phase 1: bounding box of (tensor > THRESH) per batch.
// PARTS blocks per batch; fixed 16-iteration loop unrolled x4 with
// front-batched float4 loads (MLP ~ 4), all state in scalars (no local arrays).
// ---------------------------------------------------------------------------
__global__ void __launch_bounds__(256) bounds_kernel(const float* __restrict__ tensor) {
    const int b    = blockIdx.x / PARTS;
    const int part = blockIdx.x % PARTS;
    const float4* t = reinterpret_cast<const float4*>(tensor + (size_t)b * H * W);

    const int quads_per_part = (H * W / 4) / PARTS;   // 4096
    const int iters          = quads_per_part / 256;  // 16
    const int q0 = part * quads_per_part + threadIdx.x;

    int rmin = INT_MAX, rmax = -1, cmin = INT_MAX, cmax = -1;

    #pragma unroll
    for (int i = 0; i < iters; i += 4) {
        const int qa = q0 + (i    ) * 256;
        const int qb = q0 + (i + 1) * 256;
        const int qc = q0 + (i + 2) * 256;
        const int qd = q0 + (i + 3) * 256;
        // Front-batched independent loads (register-resident scalars only).
        const float4 va = t[qa];
        const float4 vb = t[qb];
        const float4 vc = t[qc];
        const float4 vd = t[qd];
        acc_quad(va, qa, rmin, rmax, cmin, cmax);
        acc_quad(vb, qb, rmin, rmax, cmin, cmax);
        acc_quad(vc, qc, rmin, rmax, cmin, cmax);
        acc_quad(vd, qd, rmin, rmax, cmin, cmax);
    }

    // Warp reduction (signed-safe sentinels).
    #pragma unroll
    for (int o = 16; o; o >>= 1) {
        rmin = min(rmin, __shfl_xor_sync(0xffffffffu, rmin, o));
        rmax = max(rmax, __shfl_xor_sync(0xffffffffu, rmax, o));
        cmin = min(cmin, __shfl_xor_sync(0xffffffffu, cmin, o));
        cmax = max(cmax, __shfl_xor_sync(0xffffffffu, cmax, o));
    }

    __shared__ int4 s[8];   // 256 threads = 8 warps
    const int wid = threadIdx.x >> 5;
    if ((threadIdx.x & 31) == 0) s[wid] = make_int4(rmin, rmax, cmin, cmax);
    __syncthreads();

    if (threadIdx.x == 0) {
        int4 r = s[0];
        #pragma unroll
        for (int k = 1; k < 8; k++) {
            r.x = min(r.x, s[k].x); r.y = max(r.y, s[k].y);
            r.z = min(r.z, s[k].z); r.w = max(r.w, s[k].w);
        }
        g_part[blockIdx.x] = r;   // plain store: no init kernel, no atomics
    }
}

// ---------------------------------------------------------------------------
// Phase 2: bilinear crop-resize. One thread per output element (b,r,c,ch).
// ---------------------------------------------------------------------------
__device__ __forceinline__ void axis_coords(int lo, int hi, int i,
                                            int& j0, int& j1, float& w) {
    // Matches reference exactly: size = hi - lo (NOT +1);
    // src = (i+0.5)*size/OUT - 0.5, clipped to [0, max(size-1,0)];
    // i1 = min(i0+1, max(size-1, 0)).
    const float size = (float)(hi - lo);
    float src = ((float)i + 0.5f) * size / (float)OUTD - 0.5f;
    src = fminf(fmaxf(src, 0.0f), fmaxf(size - 1.0f, 0.0f));
    const int i0 = (int)src;                          // src >= 0: trunc == floor
    const int i1 = min(i0 + 1, max(hi - lo - 1, 0));
    w  = src - (float)i0;
    j0 = lo + i0;
    j1 = lo + i1;
}

__global__ void __launch_bounds__(256) resize_kernel(const float* __restrict__ img,
                                                     float* __restrict__ out) {
    // Each block lies entirely inside one batch (480000 = 1875 * 256).
    const int b = blockIdx.x / BLK_PER_BATCH;

    __shared__ int4 sb;   // reduced bounds for this batch
    if (threadIdx.x == 0) {
        int4 r = g_part[b * PARTS];
        #pragma unroll
        for (int k = 1; k < PARTS; k++) {
            const int4 p = g_part[b * PARTS + k];
            r.x = min(r.x, p.x); r.y = max(r.y, p.y);
            r.z = min(r.z, p.z); r.w = max(r.w, p.w);
        }
        if (r.y < 0) r = make_int4(0, H - 1, 0, W - 1);  // empty mask => full frame
        sb = r;
    }
    __syncthreads();
    const int4 bb = sb;

    const int idx = blockIdx.x * blockDim.x + threadIdx.x;
    const int ch = idx % 3;
    int t = idx / 3;
    const int c = t % OUTD; t /= OUTD;
    const int r = t % OUTD;
    // (t / OUTD == b by construction)

    int r0, r1, c0, c1;
    float wr, wc;
    axis_coords(bb.x, bb.y, r, r0, r1, wr);
    axis_coords(bb.z, bb.w, c, c0, c1, wc);

    const float* p = img + (size_t)b * (H * W * 3) + ch;
    const float a00 = __ldg(p + (r0 * W + c0) * 3);
    const float a01 = __ldg(p + (r0 * W + c1) * 3);
    const float a10 = __ldg(p + (r1 * W + c0) * 3);
    const float a11 = __ldg(p + (r1 * W + c1) * 3);

    const float top = fmaf(wc, a01 - a00, a00);
    const float bot = fmaf(wc, a11 - a10, a10);
    out[idx] = fmaf(wr, bot - top, top);
}

extern "C" void kernel_launch(void* const* d_in, const int* in_sizes, int n_in,
                              void* d_out, int out_size) {
    const float* image  = (const float*)d_in[0];
    const float* tensor = (const float*)d_in[1];
    // Defensive: image (25,165,824 elems) must be the larger buffer.
    if (n_in >= 2 && in_sizes[0] < in_sizes[1]) {
        const float* tmp = image; image = tensor; tensor = tmp;
    }
    float* out = (float*)d_out;

    bounds_kernel<<<NB * PARTS, 256>>>(tensor);
    resize_kernel<<<NB * BLK_PER_BATCH, 256>>>(image, out);
    (void)out_size;
}

// round 5
// speedup vs baseline: 1.9955x; 1.9955x over previous
#include <cuda_runtime.h>
#include <climits>

#define NB 32
#define H 512
#define W 512
#define OUTD 400
#define THRESH 0.7f
#define PARTS 16             // bounds blocks per batch
#define PIX_PER_BATCH 160000 // 400*400
#define BLKS_PER_BATCH 625   // 160000 / 256

// Per-(batch,part) partial bounds: {rmin, rmax, cmin, cmax}. rmax = -1 => no hit.
__device__ int4 g_part[NB * PARTS];
// Per-batch axis tables: {j0, j1, bitcast(w), 0} per output row / col.
__device__ int4 g_rtab[NB * OUTD];
__device__ int4 g_ctab[NB * OUTD];

// ---------------------------------------------------------------------------
// Phase 1: partial bounding boxes of (tensor > THRESH).
// ---------------------------------------------------------------------------
__device__ __forceinline__ void acc_quad(const float4 v, const int q,
                                         int& rmin, int& rmax,
                                         int& cmin, int& cmax) {
    if (v.x > THRESH || v.y > THRESH || v.z > THRESH || v.w > THRESH) {
        const int e = q * 4;
        const int h = e >> 9;     // W = 512
        const int w = e & 511;    // quads never straddle a row (512 % 4 == 0)
        rmin = min(rmin, h); rmax = max(rmax, h);
        if (v.x > THRESH) { cmin = min(cmin, w    ); cmax = max(cmax, w    ); }
        if (v.y > THRESH) { cmin = min(cmin, w + 1); cmax = max(cmax, w + 1); }
        if (v.z > THRESH) { cmin = min(cmin, w + 2); cmax = max(cmax, w + 2); }
        if (v.w > THRESH) { cmin = min(cmin, w + 3); cmax = max(cmax, w + 3); }
    }
}

__global__ void __launch_bounds__(256) bounds_kernel(const float* __restrict__ tensor) {
    const int b    = blockIdx.x / PARTS;
    const int part = blockIdx.x % PARTS;
    const float4* t = reinterpret_cast<const float4*>(tensor + (size_t)b * H * W);

    const int quads_per_part = (H * W / 4) / PARTS;   // 4096
    const int iters          = quads_per_part / 256;  // 16
    const int q0 = part * quads_per_part + threadIdx.x;

    int rmin = INT_MAX, rmax = -1, cmin = INT_MAX, cmax = -1;

    #pragma unroll
    for (int i = 0; i < iters; i += 4) {
        const int qa = q0 + (i    ) * 256;
        const int qb = q0 + (i + 1) * 256;
        const int qc = q0 + (i + 2) * 256;
        const int qd = q0 + (i + 3) * 256;
        const float4 va = t[qa];
        const float4 vb = t[qb];
        const float4 vc = t[qc];
        const float4 vd = t[qd];
        acc_quad(va, qa, rmin, rmax, cmin, cmax);
        acc_quad(vb, qb, rmin, rmax, cmin, cmax);
        acc_quad(vc, qc, rmin, rmax, cmin, cmax);
        acc_quad(vd, qd, rmin, rmax, cmin, cmax);
    }

    #pragma unroll
    for (int o = 16; o; o >>= 1) {
        rmin = min(rmin, __shfl_xor_sync(0xffffffffu, rmin, o));
        rmax = max(rmax, __shfl_xor_sync(0xffffffffu, rmax, o));
        cmin = min(cmin, __shfl_xor_sync(0xffffffffu, cmin, o));
        cmax = max(cmax, __shfl_xor_sync(0xffffffffu, cmax, o));
    }

    __shared__ int4 s[8];
    const int wid = threadIdx.x >> 5;
    if ((threadIdx.x & 31) == 0) s[wid] = make_int4(rmin, rmax, cmin, cmax);
    __syncthreads();

    if (threadIdx.x == 0) {
        int4 r = s[0];
        #pragma unroll
        for (int k = 1; k < 8; k++) {
            r.x = min(r.x, s[k].x); r.y = max(r.y, s[k].y);
            r.z = min(r.z, s[k].z); r.w = max(r.w, s[k].w);
        }
        g_part[blockIdx.x] = r;
    }
}

// ---------------------------------------------------------------------------
// Phase 2: reduce partials; build per-batch axis lookup tables.
// ---------------------------------------------------------------------------
__device__ __forceinline__ int4 axis_entry(int lo, int hi, int i) {
    // Matches reference exactly: size = hi - lo (NOT +1);
    // src = (i+0.5)*size/OUT - 0.5, clipped to [0, max(size-1,0)];
    // i1 = min(i0+1, max(size-1, 0)).
    const float size = (float)(hi - lo);
    float src = ((float)i + 0.5f) * size / (float)OUTD - 0.5f;
    src = fminf(fmaxf(src, 0.0f), fmaxf(size - 1.0f, 0.0f));
    const int i0 = (int)src;                          // src >= 0: trunc == floor
    const int i1 = min(i0 + 1, max(hi - lo - 1, 0));
    const float w = src - (float)i0;
    return make_int4(lo + i0, lo + i1, __float_as_int(w), 0);
}

__global__ void __launch_bounds__(256) table_kernel() {
    const int b = blockIdx.x;

    __shared__ int4 sb;
    if (threadIdx.x == 0) {
        int4 r = g_part[b * PARTS];
        #pragma unroll
        for (int k = 1; k < PARTS; k++) {
            const int4 p = g_part[b * PARTS + k];
            r.x = min(r.x, p.x); r.y = max(r.y, p.y);
            r.z = min(r.z, p.z); r.w = max(r.w, p.w);
        }
        if (r.y < 0) r = make_int4(0, H - 1, 0, W - 1);  // empty mask => full frame
        sb = r;
    }
    __syncthreads();
    const int4 bb = sb;

    for (int i = threadIdx.x; i < 2 * OUTD; i += blockDim.x) {
        if (i < OUTD) g_rtab[b * OUTD + i] = axis_entry(bb.x, bb.y, i);
        else          g_ctab[b * OUTD + i - OUTD] = axis_entry(bb.z, bb.w, i - OUTD);
    }
}

// ---------------------------------------------------------------------------
// Phase 3: bilinear crop-resize. One thread per output PIXEL (all 3 channels).
// All coordinate math comes from the tables; per-pixel work is 2 table loads,
// 12 front-batched gathers, 9 lerps, 3 stores.
// ---------------------------------------------------------------------------
__global__ void __launch_bounds__(256) resize_kernel(const float* __restrict__ img,
                                                     float* __restrict__ out) {
    const int b = blockIdx.y;
    const int q = blockIdx.x * blockDim.x + threadIdx.x;   // pixel within batch
    const int r = q / OUTD;
    const int c = q % OUTD;

    const int4 rt = g_rtab[b * OUTD + r];   // LDG.128, warp-broadcast heavy
    const int4 ct = g_ctab[b * OUTD + c];   // LDG.128, consecutive
    const float wr = __int_as_float(rt.z);
    const float wc = __int_as_float(ct.z);

    const float* base = img + (size_t)b * (H * W * 3);
    const float* p00 = base + (rt.x * W + ct.x) * 3;
    const float* p01 = base + (rt.x * W + ct.y) * 3;
    const float* p10 = base + (rt.y * W + ct.x) * 3;
    const float* p11 = base + (rt.y * W + ct.y) * 3;

    // 12 independent loads, front-batched for MLP.
    const float a00x = __ldg(p00    ), a00y = __ldg(p00 + 1), a00z = __ldg(p00 + 2);
    const float a01x = __ldg(p01    ), a01y = __ldg(p01 + 1), a01z = __ldg(p01 + 2);
    const float a10x = __ldg(p10    ), a10y = __ldg(p10 + 1), a10z = __ldg(p10 + 2);
    const float a11x = __ldg(p11    ), a11y = __ldg(p11 + 1), a11z = __ldg(p11 + 2);

    const float tx = fmaf(wc, a01x - a00x, a00x);
    const float ty = fmaf(wc, a01y - a00y, a00y);
    const float tz = fmaf(wc, a01z - a00z, a00z);
    const float bx = fmaf(wc, a11x - a10x, a10x);
    const float by = fmaf(wc, a11y - a10y, a10y);
    const float bz = fmaf(wc, a11z - a10z, a10z);

    float* o = out + ((size_t)b * PIX_PER_BATCH + q) * 3;
    o[0] = fmaf(wr, bx - tx, tx);
    o[1] = fmaf(wr, by - ty, ty);
    o[2] = fmaf(wr, bz - tz, tz);
}

extern "C" void kernel_launch(void* const* d_in, const int* in_sizes, int n_in,
                              void* d_out, int out_size) {
    const float* image  = (const float*)d_in[0];
    const float* tensor = (const float*)d_in[1];
    // Defensive: image (25,165,824 elems) must be the larger buffer.
    if (n_in >= 2 && in_sizes[0] < in_sizes[1]) {
        const float* tmp = image; image = tensor; tensor = tmp;
    }
    float* out = (float*)d_out;

    bounds_kernel<<<NB * PARTS, 256>>>(tensor);
    table_kernel<<<NB, 256>>>();
    resize_kernel<<<dim3(BLKS_PER_BATCH, NB), 256>>>(image, out);
    (void)out_size;
}